// round 16
// baseline (speedup 1.0000x reference)
#include <cuda_runtime.h>
#include <cuda_fp16.h>

#define N_NODES 100000
#define E_MAX   3400000

// ---------------- scratch (device globals; no allocation allowed) ------------
__device__ int   g_cnt[N_NODES];
__device__ int   g_start[N_NODES];   // CSR segment start (order-free assignment)
__device__ float g_dinv[N_NODES];
__device__ int   g_total;
__device__ int   g_ctr1, g_ctr2;     // dynamic work cursors for the two aggs
__device__ int   g_rank[E_MAX];      // edge's rank within its dst segment
__device__ __align__(16) int g_csr[E_MAX];   // src indices grouped by dst
__device__ __align__(16) __half g_h1[(size_t)N_NODES * 128];  // dinv-premultiplied fp16
__device__ __align__(16) __half g_a1[(size_t)N_NODES * 128];  // fp16 layer-1 activation
__device__ __align__(16) __half g_h2[(size_t)N_NODES * 64];   // dinv-premultiplied fp16
__device__ int   g_is64;

__device__ __forceinline__ unsigned to_tf32(float f) {
    unsigned r;
    asm("cvt.rna.tf32.f32 %0, %1;" : "=r"(r) : "f"(f));
    return r;
}

// ---------------- edge dtype detection (1 block) + counter zeroing ------------
__global__ void detect_kernel(const long long* __restrict__ edges) {
    __shared__ int bad;
    if (threadIdx.x == 0) { bad = 0; g_total = 0; g_ctr1 = 0; g_ctr2 = 0; }
    __syncthreads();
    for (int k = threadIdx.x; k < 1024; k += blockDim.x) {
        long long v = edges[k];
        if (v < 0 || v >= N_NODES) bad = 1;   // benign race: all writers store 1
    }
    __syncthreads();
    if (threadIdx.x == 0) g_is64 = bad ? 0 : 1;
}

// count in-degree; returned old value IS this edge's rank within its segment.
__global__ void count_kernel(const void* __restrict__ edges, int E) {
    int e = blockIdx.x * blockDim.x + threadIdx.x;
    if (e >= E) return;
    int d;
    if (g_is64) d = (int)((const long long*)edges)[(size_t)E + e];
    else        d = ((const int*)edges)[E + e];
    g_rank[e] = atomicAdd(&g_cnt[d], 1);
}

// Per-block exclusive scan of degrees; one global atomic per block hands each
// node a disjoint CSR segment. Also computes dinv.
__global__ void offset_kernel() {
    int i = blockIdx.x * blockDim.x + threadIdx.x;
    int c = (i < N_NODES) ? g_cnt[i] : 0;
    int lane = threadIdx.x & 31, wid = threadIdx.x >> 5;

    int v = c;
#pragma unroll
    for (int o = 1; o < 32; o <<= 1) {
        int t = __shfl_up_sync(0xFFFFFFFFu, v, o);
        if (lane >= o) v += t;
    }

    __shared__ int wsum[8], wbase[8];
    __shared__ int blockbase;
    if (lane == 31) wsum[wid] = v;
    __syncthreads();
    if (threadIdx.x == 0) {
        int run = 0;
#pragma unroll
        for (int w = 0; w < 8; w++) { wbase[w] = run; run += wsum[w]; }
        blockbase = atomicAdd(&g_total, run);
    }
    __syncthreads();

    if (i < N_NODES) {
        g_start[i] = blockbase + wbase[wid] + (v - c);
        g_dinv[i]  = rsqrtf((float)(c + 1));            // +1 = self loop
    }
}

// atomic-free fill: position comes from precomputed rank
__global__ void fill_kernel(const void* __restrict__ edges, int E) {
    int e = blockIdx.x * blockDim.x + threadIdx.x;
    if (e >= E) return;
    int s, d;
    if (g_is64) {
        const long long* p = (const long long*)edges;
        s = (int)p[e];
        d = (int)p[(size_t)E + e];
    } else {
        const int* p = (const int*)edges;
        s = p[e];
        d = p[E + e];
    }
    g_csr[g_start[d] + g_rank[e]] = s;
}

// ---------------- GEMM: Y[N,DOUT](fp16) = dinv[row] * (X[N,128] @ W) --------
// tf32 mma.sync.m16n8k8; dinv premultiplied in the epilogue so aggregation
// needs NO per-edge dinv gather. AHALF selects fp16 input staging (layer 2).
template <int DOUT, bool AHALF>
__global__ void gemm_mma_kernel(const void* __restrict__ Xv, const float* __restrict__ W,
                                __half* __restrict__ Y) {
    constexpr int XW = 128 + 4;      // padded X row (floats)
    constexpr int WW = DOUT + 4;     // padded W row
    extern __shared__ float smem[];
    float* sX = smem;                // 64 * XW
    float* sW = smem + 64 * XW;      // 128 * WW

    int tid = threadIdx.x, lane = tid & 31, wid = tid >> 5;
    int row0 = blockIdx.x * 64;

    if constexpr (!AHALF) {
        const float* X = (const float*)Xv;
        for (int i = tid; i < 64 * 32; i += 256) {
            int r = i >> 5, c4 = (i & 31) * 4;
            int gr = row0 + r; if (gr >= N_NODES) gr = N_NODES - 1;
            float4 v = *(const float4*)&X[(size_t)gr * 128 + c4];
            float* dst = &sX[r * XW + c4];
            dst[0] = __uint_as_float(to_tf32(v.x));
            dst[1] = __uint_as_float(to_tf32(v.y));
            dst[2] = __uint_as_float(to_tf32(v.z));
            dst[3] = __uint_as_float(to_tf32(v.w));
        }
    } else {
        const __half* X = (const __half*)Xv;
        for (int i = tid; i < 64 * 32; i += 256) {
            int r = i >> 5, c4 = (i & 31) * 4;
            int gr = row0 + r; if (gr >= N_NODES) gr = N_NODES - 1;
            uint2 v = *(const uint2*)&X[(size_t)gr * 128 + c4];
            __half2 a = *(__half2*)&v.x, b = *(__half2*)&v.y;
            float* dst = &sX[r * XW + c4];
            dst[0] = __uint_as_float(to_tf32(__low2float(a)));
            dst[1] = __uint_as_float(to_tf32(__high2float(a)));
            dst[2] = __uint_as_float(to_tf32(__low2float(b)));
            dst[3] = __uint_as_float(to_tf32(__high2float(b)));
        }
    }
    for (int i = tid; i < 128 * (DOUT / 4); i += 256) {
        int r = i / (DOUT / 4), c4 = (i % (DOUT / 4)) * 4;
        float4 v = *(const float4*)&W[(size_t)r * DOUT + c4];
        float* dst = &sW[r * WW + c4];
        dst[0] = __uint_as_float(to_tf32(v.x));
        dst[1] = __uint_as_float(to_tf32(v.y));
        dst[2] = __uint_as_float(to_tf32(v.z));
        dst[3] = __uint_as_float(to_tf32(v.w));
    }
    __syncthreads();

    constexpr int NT = DOUT / 16;    // m16n8 tiles per warp
    int wr = (wid & 3) * 16;
    int wn = (wid >> 2) * (DOUT / 2);
    int g = lane >> 2, tig = lane & 3;

    float c[NT][4];
#pragma unroll
    for (int nt = 0; nt < NT; nt++)
#pragma unroll
        for (int j = 0; j < 4; j++) c[nt][j] = 0.0f;

#pragma unroll
    for (int ks = 0; ks < 16; ks++) {
        int k0 = ks * 8;
        unsigned a0 = __float_as_uint(sX[(wr + g)     * XW + k0 + tig]);
        unsigned a1 = __float_as_uint(sX[(wr + g + 8) * XW + k0 + tig]);
        unsigned a2 = __float_as_uint(sX[(wr + g)     * XW + k0 + tig + 4]);
        unsigned a3 = __float_as_uint(sX[(wr + g + 8) * XW + k0 + tig + 4]);
#pragma unroll
        for (int nt = 0; nt < NT; nt++) {
            unsigned b0 = __float_as_uint(sW[(k0 + tig)     * WW + wn + nt * 8 + g]);
            unsigned b1 = __float_as_uint(sW[(k0 + tig + 4) * WW + wn + nt * 8 + g]);
            asm("mma.sync.aligned.m16n8k8.row.col.f32.tf32.tf32.f32 "
                "{%0,%1,%2,%3}, {%4,%5,%6,%7}, {%8,%9}, {%0,%1,%2,%3};"
                : "+f"(c[nt][0]), "+f"(c[nt][1]), "+f"(c[nt][2]), "+f"(c[nt][3])
                : "r"(a0), "r"(a1), "r"(a2), "r"(a3), "r"(b0), "r"(b1));
        }
    }

    int r1 = row0 + wr + g;
    int r2 = r1 + 8;
    float d1 = (r1 < N_NODES) ? g_dinv[r1] : 0.0f;
    float d2 = (r2 < N_NODES) ? g_dinv[r2] : 0.0f;
#pragma unroll
    for (int nt = 0; nt < NT; nt++) {
        int col = wn + nt * 8 + tig * 2;
        __half2 p0 = __floats2half2_rn(c[nt][0] * d1, c[nt][1] * d1);
        __half2 p1 = __floats2half2_rn(c[nt][2] * d2, c[nt][3] * d2);
        if (r1 < N_NODES) *(unsigned*)&Y[(size_t)r1 * DOUT + col] = *(unsigned*)&p0;
        if (r2 < N_NODES) *(unsigned*)&Y[(size_t)r2 * DOUT + col] = *(unsigned*)&p1;
    }
}

// ---------------- agg layer 1: D=128, split-warp gathers, dynamic work -------
// Persistent warps grab 4-node chunks from a global cursor -> near-perfect
// load balance (R15 lesson: per-block max-of-warps imbalance was the tax).
__global__ void agg128_kernel(const __half* __restrict__ H, const float* __restrict__ bias,
                              __half* __restrict__ OUT) {
    int lane = threadIdx.x & 31;
    int g = lane >> 4;        // half-warp id (edge parity)
    int sub = lane & 15;      // 16 lanes x 8 halves = 128 cols

    for (;;) {
        int base;
        if (lane == 0) base = atomicAdd(&g_ctr1, 4);
        base = __shfl_sync(0xFFFFFFFFu, base, 0);
        if (base >= N_NODES) return;
        int nend = base + 4; if (nend > N_NODES) nend = N_NODES;

        for (int gw = base; gw < nend; gw++) {
            float acc[8];
            if (g == 0) {     // seed with own premultiplied row (self-loop)
                uint4 v = *(const uint4*)&H[(size_t)gw * 128 + sub * 8];
                __half2 h0 = *(__half2*)&v.x, h1 = *(__half2*)&v.y;
                __half2 h2v = *(__half2*)&v.z, h3 = *(__half2*)&v.w;
                acc[0] = __low2float(h0); acc[1] = __high2float(h0);
                acc[2] = __low2float(h1); acc[3] = __high2float(h1);
                acc[4] = __low2float(h2v); acc[5] = __high2float(h2v);
                acc[6] = __low2float(h3); acc[7] = __high2float(h3);
            } else {
#pragma unroll
                for (int j = 0; j < 8; j++) acc[j] = 0.0f;
            }

            int e = g_start[gw];
            const int e1 = e + g_cnt[gw];

            for (; e + 3 < e1; e += 4) {
                int sa = __ldg(&g_csr[e + g]);
                int sb = __ldg(&g_csr[e + 2 + g]);
                uint4 va = *(const uint4*)&H[(size_t)sa * 128 + sub * 8];
                uint4 vb = *(const uint4*)&H[(size_t)sb * 128 + sub * 8];
                __half2 t0 = __hadd2(*(__half2*)&va.x, *(__half2*)&vb.x);
                __half2 t1 = __hadd2(*(__half2*)&va.y, *(__half2*)&vb.y);
                __half2 t2 = __hadd2(*(__half2*)&va.z, *(__half2*)&vb.z);
                __half2 t3 = __hadd2(*(__half2*)&va.w, *(__half2*)&vb.w);
                acc[0] += __low2float(t0); acc[1] += __high2float(t0);
                acc[2] += __low2float(t1); acc[3] += __high2float(t1);
                acc[4] += __low2float(t2); acc[5] += __high2float(t2);
                acc[6] += __low2float(t3); acc[7] += __high2float(t3);
            }
            for (; e < e1; e++) {
                if (g == 0) {
                    int s = __ldg(&g_csr[e]);
                    uint4 v = *(const uint4*)&H[(size_t)s * 128 + sub * 8];
                    __half2 h0 = *(__half2*)&v.x, h1 = *(__half2*)&v.y;
                    __half2 h2v = *(__half2*)&v.z, h3 = *(__half2*)&v.w;
                    acc[0] += __low2float(h0); acc[1] += __high2float(h0);
                    acc[2] += __low2float(h1); acc[3] += __high2float(h1);
                    acc[4] += __low2float(h2v); acc[5] += __high2float(h2v);
                    acc[6] += __low2float(h3); acc[7] += __high2float(h3);
                }
            }

#pragma unroll
            for (int j = 0; j < 8; j++)
                acc[j] += __shfl_xor_sync(0xFFFFFFFFu, acc[j], 16);

            if (g == 0) {
                float dd = g_dinv[gw];
                float4 b0 = *(const float4*)&bias[sub * 8];
                float4 b1 = *(const float4*)&bias[sub * 8 + 4];
                float o0 = fmaxf(fmaf(dd, acc[0], b0.x), 0.0f);
                float o1 = fmaxf(fmaf(dd, acc[1], b0.y), 0.0f);
                float o2 = fmaxf(fmaf(dd, acc[2], b0.z), 0.0f);
                float o3 = fmaxf(fmaf(dd, acc[3], b0.w), 0.0f);
                float o4 = fmaxf(fmaf(dd, acc[4], b1.x), 0.0f);
                float o5 = fmaxf(fmaf(dd, acc[5], b1.y), 0.0f);
                float o6 = fmaxf(fmaf(dd, acc[6], b1.z), 0.0f);
                float o7 = fmaxf(fmaf(dd, acc[7], b1.w), 0.0f);
                __half2 p0 = __floats2half2_rn(o0, o1);
                __half2 p1 = __floats2half2_rn(o2, o3);
                __half2 p2 = __floats2half2_rn(o4, o5);
                __half2 p3 = __floats2half2_rn(o6, o7);
                uint4 pk;
                pk.x = *(unsigned*)&p0; pk.y = *(unsigned*)&p1;
                pk.z = *(unsigned*)&p2; pk.w = *(unsigned*)&p3;
                *(uint4*)&OUT[(size_t)gw * 128 + sub * 8] = pk;
            }
        }
    }
}

// ---------------- agg layer 2: D=64, quarter-warp gathers, dynamic work ------
__global__ void agg64_kernel(const __half* __restrict__ H, const float* __restrict__ bias,
                             float* __restrict__ OUT) {
    int lane = threadIdx.x & 31;
    int g4 = lane >> 3;       // quarter-warp id (edge slot 0-3)
    int sub = lane & 7;       // 8 lanes x 8 halves = 64 cols

    for (;;) {
        int base;
        if (lane == 0) base = atomicAdd(&g_ctr2, 4);
        base = __shfl_sync(0xFFFFFFFFu, base, 0);
        if (base >= N_NODES) return;
        int nend = base + 4; if (nend > N_NODES) nend = N_NODES;

        for (int gw = base; gw < nend; gw++) {
            float acc[8];
            if (g4 == 0) {    // seed with own premultiplied row (self-loop)
                uint4 v = *(const uint4*)&H[(size_t)gw * 64 + sub * 8];
                __half2 h0 = *(__half2*)&v.x, h1 = *(__half2*)&v.y;
                __half2 h2v = *(__half2*)&v.z, h3 = *(__half2*)&v.w;
                acc[0] = __low2float(h0); acc[1] = __high2float(h0);
                acc[2] = __low2float(h1); acc[3] = __high2float(h1);
                acc[4] = __low2float(h2v); acc[5] = __high2float(h2v);
                acc[6] = __low2float(h3); acc[7] = __high2float(h3);
            } else {
#pragma unroll
                for (int j = 0; j < 8; j++) acc[j] = 0.0f;
            }

            int e = g_start[gw];
            const int e1 = e + g_cnt[gw];

            for (; e + 3 < e1; e += 4) {
                int s = __ldg(&g_csr[e + g4]);
                uint4 v = *(const uint4*)&H[(size_t)s * 64 + sub * 8];
                __half2 h0 = *(__half2*)&v.x, h1 = *(__half2*)&v.y;
                __half2 h2v = *(__half2*)&v.z, h3 = *(__half2*)&v.w;
                acc[0] += __low2float(h0); acc[1] += __high2float(h0);
                acc[2] += __low2float(h1); acc[3] += __high2float(h1);
                acc[4] += __low2float(h2v); acc[5] += __high2float(h2v);
                acc[6] += __low2float(h3); acc[7] += __high2float(h3);
            }
            for (; e < e1; e++) {
                if (g4 == 0) {
                    int s = __ldg(&g_csr[e]);
                    uint4 v = *(const uint4*)&H[(size_t)s * 64 + sub * 8];
                    __half2 h0 = *(__half2*)&v.x, h1 = *(__half2*)&v.y;
                    __half2 h2v = *(__half2*)&v.z, h3 = *(__half2*)&v.w;
                    acc[0] += __low2float(h0); acc[1] += __high2float(h0);
                    acc[2] += __low2float(h1); acc[3] += __high2float(h1);
                    acc[4] += __low2float(h2v); acc[5] += __high2float(h2v);
                    acc[6] += __low2float(h3); acc[7] += __high2float(h3);
                }
            }

#pragma unroll
            for (int j = 0; j < 8; j++)
                acc[j] += __shfl_xor_sync(0xFFFFFFFFu, acc[j], 8);
#pragma unroll
            for (int j = 0; j < 8; j++)
                acc[j] += __shfl_xor_sync(0xFFFFFFFFu, acc[j], 16);

            if (g4 == 0) {
                float dd = g_dinv[gw];
                float4 b0 = *(const float4*)&bias[sub * 8];
                float4 b1 = *(const float4*)&bias[sub * 8 + 4];
                float4 o0, o1;
                o0.x = fmaf(dd, acc[0], b0.x); o0.y = fmaf(dd, acc[1], b0.y);
                o0.z = fmaf(dd, acc[2], b0.z); o0.w = fmaf(dd, acc[3], b0.w);
                o1.x = fmaf(dd, acc[4], b1.x); o1.y = fmaf(dd, acc[5], b1.y);
                o1.z = fmaf(dd, acc[6], b1.z); o1.w = fmaf(dd, acc[7], b1.w);
                *(float4*)&OUT[(size_t)gw * 64 + sub * 8]     = o0;
                *(float4*)&OUT[(size_t)gw * 64 + sub * 8 + 4] = o1;
            }
        }
    }
}

// ---------------- launch -----------------------------------------------------
extern "C" void kernel_launch(void* const* d_in, const int* in_sizes, int n_in,
                              void* d_out, int out_size) {
    const float* x  = (const float*)d_in[0];
    const void*  ei = d_in[1];
    const float* W1 = (const float*)d_in[2];
    const float* b1 = (const float*)d_in[3];
    const float* W2 = (const float*)d_in[4];
    const float* b2 = (const float*)d_in[5];
    float* out = (float*)d_out;
    int E = in_sizes[1] / 2;

    const int SMEM1 = (64 * 132 + 128 * 132) * 4;   // ~99 KB
    const int SMEM2 = (64 * 132 + 128 * 68) * 4;    // ~67 KB
    cudaFuncSetAttribute(gemm_mma_kernel<128, false>, cudaFuncAttributeMaxDynamicSharedMemorySize, SMEM1);
    cudaFuncSetAttribute(gemm_mma_kernel<64, true>,   cudaFuncAttributeMaxDynamicSharedMemorySize, SMEM2);

    __half *h1, *h2, *a1;
    int *cnt_p;
    cudaGetSymbolAddress((void**)&h1, g_h1);
    cudaGetSymbolAddress((void**)&a1, g_a1);
    cudaGetSymbolAddress((void**)&h2, g_h2);
    cudaGetSymbolAddress((void**)&cnt_p, g_cnt);

    const int TB = 256;
    int gE = (E + TB - 1) / TB;
    int gN = (N_NODES + TB - 1) / TB;
    int gG = (N_NODES + 63) / 64;
    const int AGG_BLOCKS = 148 * 8;   // persistent-style fill of the chip

    // Serial single-stream schedule: overlapping bandwidth-heavy phases
    // thrashes L2 on this chip (measured +268us in R2). Keep phases ordered.
    cudaMemsetAsync(cnt_p, 0, N_NODES * sizeof(int), 0);
    detect_kernel<<<1, 256>>>((const long long*)ei);  // zeroes g_total + cursors
    count_kernel<<<gE, TB>>>(ei, E);          // also records per-edge rank
    offset_kernel<<<gN, TB>>>();              // block-scan + 391 atomics + dinv
    fill_kernel<<<gE, TB>>>(ei, E);           // atomic-free scatter

    gemm_mma_kernel<128, false><<<gG, 256, SMEM1>>>(x, W1, h1);
    agg128_kernel<<<AGG_BLOCKS, 256>>>(h1, b1, a1);
    gemm_mma_kernel<64, true><<<gG, 256, SMEM2>>>(a1, W2, h2);
    agg64_kernel<<<AGG_BLOCKS, 256>>>(h2, b2, out);
}

// round 17
// speedup vs baseline: 1.0777x; 1.0777x over previous
#include <cuda_runtime.h>
#include <cuda_fp16.h>

#define N_NODES 100000
#define E_MAX   3400000
#define RANK_PACK 8192           // pack = dst*RANK_PACK + rank; max degree << 8192

// ---------------- scratch (device globals; no allocation allowed) ------------
__device__ int   g_cnt[N_NODES];
__device__ int   g_start[N_NODES];   // CSR segment start (order-free assignment)
__device__ float g_dinv[N_NODES];
__device__ int   g_total;
__device__ int   g_pack[E_MAX];      // packed (dst, rank-within-dst-segment)
__device__ __align__(16) int g_csr[E_MAX];   // src indices grouped by dst
__device__ __align__(16) __half g_h1[(size_t)N_NODES * 128];  // dinv-premultiplied fp16
__device__ __align__(16) __half g_a1[(size_t)N_NODES * 128];  // fp16 layer-1 activation
__device__ __align__(16) __half g_h2[(size_t)N_NODES * 64];   // dinv-premultiplied fp16
__device__ int   g_is64;

__device__ __forceinline__ unsigned to_tf32(float f) {
    unsigned r;
    asm("cvt.rna.tf32.f32 %0, %1;" : "=r"(r) : "f"(f));
    return r;
}

// ---------------- edge dtype detection (1 block) + g_total zero ---------------
__global__ void detect_kernel(const long long* __restrict__ edges) {
    __shared__ int bad;
    if (threadIdx.x == 0) { bad = 0; g_total = 0; }
    __syncthreads();
    for (int k = threadIdx.x; k < 1024; k += blockDim.x) {
        long long v = edges[k];
        if (v < 0 || v >= N_NODES) bad = 1;   // benign race: all writers store 1
    }
    __syncthreads();
    if (threadIdx.x == 0) g_is64 = bad ? 0 : 1;
}

// count in-degree; atomic's return value IS this edge's rank within its dst
// segment. Pack (dst, rank) so fill never re-reads the dst row of the edges.
__global__ void count_kernel(const void* __restrict__ edges, int E) {
    int e = blockIdx.x * blockDim.x + threadIdx.x;
    if (e >= E) return;
    int d;
    if (g_is64) d = (int)((const long long*)edges)[(size_t)E + e];
    else        d = ((const int*)edges)[E + e];
    int r = atomicAdd(&g_cnt[d], 1);
    g_pack[e] = d * RANK_PACK + r;
}

// Per-block exclusive scan of degrees; one global atomic per block hands each
// node a disjoint CSR segment. Also computes dinv.
__global__ void offset_kernel() {
    int i = blockIdx.x * blockDim.x + threadIdx.x;
    int c = (i < N_NODES) ? g_cnt[i] : 0;
    int lane = threadIdx.x & 31, wid = threadIdx.x >> 5;

    int v = c;
#pragma unroll
    for (int o = 1; o < 32; o <<= 1) {
        int t = __shfl_up_sync(0xFFFFFFFFu, v, o);
        if (lane >= o) v += t;
    }

    __shared__ int wsum[8], wbase[8];
    __shared__ int blockbase;
    if (lane == 31) wsum[wid] = v;
    __syncthreads();
    if (threadIdx.x == 0) {
        int run = 0;
#pragma unroll
        for (int w = 0; w < 8; w++) { wbase[w] = run; run += wsum[w]; }
        blockbase = atomicAdd(&g_total, run);
    }
    __syncthreads();

    if (i < N_NODES) {
        g_start[i] = blockbase + wbase[wid] + (v - c);
        g_dinv[i]  = rsqrtf((float)(c + 1));            // +1 = self loop
    }
}

// atomic-free fill: dst+rank come from the packed word; reads only src row
__global__ void fill_kernel(const void* __restrict__ edges, int E) {
    int e = blockIdx.x * blockDim.x + threadIdx.x;
    if (e >= E) return;
    int s;
    if (g_is64) s = (int)((const long long*)edges)[e];
    else        s = ((const int*)edges)[e];
    int pk = g_pack[e];
    int d = pk / RANK_PACK;
    int r = pk - d * RANK_PACK;
    g_csr[g_start[d] + r] = s;
}

// ---------------- GEMM: Y[N,DOUT](fp16) = dinv[row] * (X[N,128] @ W) --------
// tf32 mma.sync.m16n8k8; dinv premultiplied in the epilogue so aggregation
// needs NO per-edge dinv gather. AHALF selects fp16 input staging (layer 2).
template <int DOUT, bool AHALF>
__global__ void gemm_mma_kernel(const void* __restrict__ Xv, const float* __restrict__ W,
                                __half* __restrict__ Y) {
    constexpr int XW = 128 + 4;      // padded X row (floats)
    constexpr int WW = DOUT + 4;     // padded W row
    extern __shared__ float smem[];
    float* sX = smem;                // 64 * XW
    float* sW = smem + 64 * XW;      // 128 * WW

    int tid = threadIdx.x, lane = tid & 31, wid = tid >> 5;
    int row0 = blockIdx.x * 64;

    if constexpr (!AHALF) {
        const float* X = (const float*)Xv;
        for (int i = tid; i < 64 * 32; i += 256) {
            int r = i >> 5, c4 = (i & 31) * 4;
            int gr = row0 + r; if (gr >= N_NODES) gr = N_NODES - 1;
            float4 v = *(const float4*)&X[(size_t)gr * 128 + c4];
            float* dst = &sX[r * XW + c4];
            dst[0] = __uint_as_float(to_tf32(v.x));
            dst[1] = __uint_as_float(to_tf32(v.y));
            dst[2] = __uint_as_float(to_tf32(v.z));
            dst[3] = __uint_as_float(to_tf32(v.w));
        }
    } else {
        const __half* X = (const __half*)Xv;
        for (int i = tid; i < 64 * 32; i += 256) {
            int r = i >> 5, c4 = (i & 31) * 4;
            int gr = row0 + r; if (gr >= N_NODES) gr = N_NODES - 1;
            uint2 v = *(const uint2*)&X[(size_t)gr * 128 + c4];
            __half2 a = *(__half2*)&v.x, b = *(__half2*)&v.y;
            float* dst = &sX[r * XW + c4];
            dst[0] = __uint_as_float(to_tf32(__low2float(a)));
            dst[1] = __uint_as_float(to_tf32(__high2float(a)));
            dst[2] = __uint_as_float(to_tf32(__low2float(b)));
            dst[3] = __uint_as_float(to_tf32(__high2float(b)));
        }
    }
    for (int i = tid; i < 128 * (DOUT / 4); i += 256) {
        int r = i / (DOUT / 4), c4 = (i % (DOUT / 4)) * 4;
        float4 v = *(const float4*)&W[(size_t)r * DOUT + c4];
        float* dst = &sW[r * WW + c4];
        dst[0] = __uint_as_float(to_tf32(v.x));
        dst[1] = __uint_as_float(to_tf32(v.y));
        dst[2] = __uint_as_float(to_tf32(v.z));
        dst[3] = __uint_as_float(to_tf32(v.w));
    }
    __syncthreads();

    constexpr int NT = DOUT / 16;    // m16n8 tiles per warp
    int wr = (wid & 3) * 16;
    int wn = (wid >> 2) * (DOUT / 2);
    int g = lane >> 2, tig = lane & 3;

    float c[NT][4];
#pragma unroll
    for (int nt = 0; nt < NT; nt++)
#pragma unroll
        for (int j = 0; j < 4; j++) c[nt][j] = 0.0f;

#pragma unroll
    for (int ks = 0; ks < 16; ks++) {
        int k0 = ks * 8;
        unsigned a0 = __float_as_uint(sX[(wr + g)     * XW + k0 + tig]);
        unsigned a1 = __float_as_uint(sX[(wr + g + 8) * XW + k0 + tig]);
        unsigned a2 = __float_as_uint(sX[(wr + g)     * XW + k0 + tig + 4]);
        unsigned a3 = __float_as_uint(sX[(wr + g + 8) * XW + k0 + tig + 4]);
#pragma unroll
        for (int nt = 0; nt < NT; nt++) {
            unsigned b0 = __float_as_uint(sW[(k0 + tig)     * WW + wn + nt * 8 + g]);
            unsigned b1 = __float_as_uint(sW[(k0 + tig + 4) * WW + wn + nt * 8 + g]);
            asm("mma.sync.aligned.m16n8k8.row.col.f32.tf32.tf32.f32 "
                "{%0,%1,%2,%3}, {%4,%5,%6,%7}, {%8,%9}, {%0,%1,%2,%3};"
                : "+f"(c[nt][0]), "+f"(c[nt][1]), "+f"(c[nt][2]), "+f"(c[nt][3])
                : "r"(a0), "r"(a1), "r"(a2), "r"(a3), "r"(b0), "r"(b1));
        }
    }

    int r1 = row0 + wr + g;
    int r2 = r1 + 8;
    float d1 = (r1 < N_NODES) ? g_dinv[r1] : 0.0f;
    float d2 = (r2 < N_NODES) ? g_dinv[r2] : 0.0f;
#pragma unroll
    for (int nt = 0; nt < NT; nt++) {
        int col = wn + nt * 8 + tig * 2;
        __half2 p0 = __floats2half2_rn(c[nt][0] * d1, c[nt][1] * d1);
        __half2 p1 = __floats2half2_rn(c[nt][2] * d2, c[nt][3] * d2);
        if (r1 < N_NODES) *(unsigned*)&Y[(size_t)r1 * DOUT + col] = *(unsigned*)&p0;
        if (r2 < N_NODES) *(unsigned*)&Y[(size_t)r2 * DOUT + col] = *(unsigned*)&p1;
    }
}

// ---------------- agg layer 1: D=128, split-warp wide gathers (R15 form) -----
// Half-warps own alternate edges: 16 lanes x 16B = one 256B row per LDG.128.
// Static warp-per-node grid (R16 lesson: dynamic stealing regressed).
__global__ void agg128_kernel(const __half* __restrict__ H, const float* __restrict__ bias,
                              __half* __restrict__ OUT) {
    int gw = (blockIdx.x * blockDim.x + threadIdx.x) >> 5;
    if (gw >= N_NODES) return;
    int lane = threadIdx.x & 31;
    int g = lane >> 4;        // half-warp id (edge parity)
    int sub = lane & 15;      // 16 lanes x 8 halves = 128 cols

    float acc[8];
    if (g == 0) {             // seed with own premultiplied row (self-loop)
        uint4 v = *(const uint4*)&H[(size_t)gw * 128 + sub * 8];
        __half2 h0 = *(__half2*)&v.x, h1 = *(__half2*)&v.y;
        __half2 h2v = *(__half2*)&v.z, h3 = *(__half2*)&v.w;
        acc[0] = __low2float(h0); acc[1] = __high2float(h0);
        acc[2] = __low2float(h1); acc[3] = __high2float(h1);
        acc[4] = __low2float(h2v); acc[5] = __high2float(h2v);
        acc[6] = __low2float(h3); acc[7] = __high2float(h3);
    } else {
#pragma unroll
        for (int j = 0; j < 8; j++) acc[j] = 0.0f;
    }

    int e = g_start[gw];
    const int e1 = e + g_cnt[gw];

    // 4 edges per iteration: this half-warp handles e+g and e+2+g
    for (; e + 3 < e1; e += 4) {
        int sa = __ldg(&g_csr[e + g]);
        int sb = __ldg(&g_csr[e + 2 + g]);
        uint4 va = *(const uint4*)&H[(size_t)sa * 128 + sub * 8];
        uint4 vb = *(const uint4*)&H[(size_t)sb * 128 + sub * 8];
        __half2 t0 = __hadd2(*(__half2*)&va.x, *(__half2*)&vb.x);
        __half2 t1 = __hadd2(*(__half2*)&va.y, *(__half2*)&vb.y);
        __half2 t2 = __hadd2(*(__half2*)&va.z, *(__half2*)&vb.z);
        __half2 t3 = __hadd2(*(__half2*)&va.w, *(__half2*)&vb.w);
        acc[0] += __low2float(t0); acc[1] += __high2float(t0);
        acc[2] += __low2float(t1); acc[3] += __high2float(t1);
        acc[4] += __low2float(t2); acc[5] += __high2float(t2);
        acc[6] += __low2float(t3); acc[7] += __high2float(t3);
    }
    // tail (0-3 edges): half-warp 0 only
    for (; e < e1; e++) {
        if (g == 0) {
            int s = __ldg(&g_csr[e]);
            uint4 v = *(const uint4*)&H[(size_t)s * 128 + sub * 8];
            __half2 h0 = *(__half2*)&v.x, h1 = *(__half2*)&v.y;
            __half2 h2v = *(__half2*)&v.z, h3 = *(__half2*)&v.w;
            acc[0] += __low2float(h0); acc[1] += __high2float(h0);
            acc[2] += __low2float(h1); acc[3] += __high2float(h1);
            acc[4] += __low2float(h2v); acc[5] += __high2float(h2v);
            acc[6] += __low2float(h3); acc[7] += __high2float(h3);
        }
    }

    // combine the two half-warps
#pragma unroll
    for (int j = 0; j < 8; j++)
        acc[j] += __shfl_xor_sync(0xFFFFFFFFu, acc[j], 16);

    if (g == 0) {
        float dd = g_dinv[gw];
        float4 b0 = *(const float4*)&bias[sub * 8];
        float4 b1 = *(const float4*)&bias[sub * 8 + 4];
        float o0 = fmaxf(fmaf(dd, acc[0], b0.x), 0.0f);
        float o1 = fmaxf(fmaf(dd, acc[1], b0.y), 0.0f);
        float o2 = fmaxf(fmaf(dd, acc[2], b0.z), 0.0f);
        float o3 = fmaxf(fmaf(dd, acc[3], b0.w), 0.0f);
        float o4 = fmaxf(fmaf(dd, acc[4], b1.x), 0.0f);
        float o5 = fmaxf(fmaf(dd, acc[5], b1.y), 0.0f);
        float o6 = fmaxf(fmaf(dd, acc[6], b1.z), 0.0f);
        float o7 = fmaxf(fmaf(dd, acc[7], b1.w), 0.0f);
        __half2 p0 = __floats2half2_rn(o0, o1);
        __half2 p1 = __floats2half2_rn(o2, o3);
        __half2 p2 = __floats2half2_rn(o4, o5);
        __half2 p3 = __floats2half2_rn(o6, o7);
        uint4 pk;
        pk.x = *(unsigned*)&p0; pk.y = *(unsigned*)&p1;
        pk.z = *(unsigned*)&p2; pk.w = *(unsigned*)&p3;
        *(uint4*)&OUT[(size_t)gw * 128 + sub * 8] = pk;
    }
}

// ---------------- agg layer 2: D=64, quarter-warp gathers, fp32 out ----------
__global__ void agg64_kernel(const __half* __restrict__ H, const float* __restrict__ bias,
                             float* __restrict__ OUT) {
    int gw = (blockIdx.x * blockDim.x + threadIdx.x) >> 5;
    if (gw >= N_NODES) return;
    int lane = threadIdx.x & 31;
    int g4 = lane >> 3;       // quarter-warp id (edge slot 0-3)
    int sub = lane & 7;       // 8 lanes x 8 halves = 64 cols

    float acc[8];
    if (g4 == 0) {            // seed with own premultiplied row (self-loop)
        uint4 v = *(const uint4*)&H[(size_t)gw * 64 + sub * 8];
        __half2 h0 = *(__half2*)&v.x, h1 = *(__half2*)&v.y;
        __half2 h2v = *(__half2*)&v.z, h3 = *(__half2*)&v.w;
        acc[0] = __low2float(h0); acc[1] = __high2float(h0);
        acc[2] = __low2float(h1); acc[3] = __high2float(h1);
        acc[4] = __low2float(h2v); acc[5] = __high2float(h2v);
        acc[6] = __low2float(h3); acc[7] = __high2float(h3);
    } else {
#pragma unroll
        for (int j = 0; j < 8; j++) acc[j] = 0.0f;
    }

    int e = g_start[gw];
    const int e1 = e + g_cnt[gw];

    for (; e + 3 < e1; e += 4) {
        int s = __ldg(&g_csr[e + g4]);
        uint4 v = *(const uint4*)&H[(size_t)s * 64 + sub * 8];
        __half2 h0 = *(__half2*)&v.x, h1 = *(__half2*)&v.y;
        __half2 h2v = *(__half2*)&v.z, h3 = *(__half2*)&v.w;
        acc[0] += __low2float(h0); acc[1] += __high2float(h0);
        acc[2] += __low2float(h1); acc[3] += __high2float(h1);
        acc[4] += __low2float(h2v); acc[5] += __high2float(h2v);
        acc[6] += __low2float(h3); acc[7] += __high2float(h3);
    }
    for (; e < e1; e++) {
        if (g4 == 0) {
            int s = __ldg(&g_csr[e]);
            uint4 v = *(const uint4*)&H[(size_t)s * 64 + sub * 8];
            __half2 h0 = *(__half2*)&v.x, h1 = *(__half2*)&v.y;
            __half2 h2v = *(__half2*)&v.z, h3 = *(__half2*)&v.w;
            acc[0] += __low2float(h0); acc[1] += __high2float(h0);
            acc[2] += __low2float(h1); acc[3] += __high2float(h1);
            acc[4] += __low2float(h2v); acc[5] += __high2float(h2v);
            acc[6] += __low2float(h3); acc[7] += __high2float(h3);
        }
    }

    // combine the four quarter-warps
#pragma unroll
    for (int j = 0; j < 8; j++)
        acc[j] += __shfl_xor_sync(0xFFFFFFFFu, acc[j], 8);
#pragma unroll
    for (int j = 0; j < 8; j++)
        acc[j] += __shfl_xor_sync(0xFFFFFFFFu, acc[j], 16);

    if (g4 == 0) {
        float dd = g_dinv[gw];
        float4 b0 = *(const float4*)&bias[sub * 8];
        float4 b1 = *(const float4*)&bias[sub * 8 + 4];
        float4 o0, o1;
        o0.x = fmaf(dd, acc[0], b0.x); o0.y = fmaf(dd, acc[1], b0.y);
        o0.z = fmaf(dd, acc[2], b0.z); o0.w = fmaf(dd, acc[3], b0.w);
        o1.x = fmaf(dd, acc[4], b1.x); o1.y = fmaf(dd, acc[5], b1.y);
        o1.z = fmaf(dd, acc[6], b1.z); o1.w = fmaf(dd, acc[7], b1.w);
        *(float4*)&OUT[(size_t)gw * 64 + sub * 8]     = o0;
        *(float4*)&OUT[(size_t)gw * 64 + sub * 8 + 4] = o1;
    }
}

// ---------------- launch -----------------------------------------------------
extern "C" void kernel_launch(void* const* d_in, const int* in_sizes, int n_in,
                              void* d_out, int out_size) {
    const float* x  = (const float*)d_in[0];
    const void*  ei = d_in[1];
    const float* W1 = (const float*)d_in[2];
    const float* b1 = (const float*)d_in[3];
    const float* W2 = (const float*)d_in[4];
    const float* b2 = (const float*)d_in[5];
    float* out = (float*)d_out;
    int E = in_sizes[1] / 2;

    const int SMEM1 = (64 * 132 + 128 * 132) * 4;   // ~99 KB
    const int SMEM2 = (64 * 132 + 128 * 68) * 4;    // ~67 KB
    cudaFuncSetAttribute(gemm_mma_kernel<128, false>, cudaFuncAttributeMaxDynamicSharedMemorySize, SMEM1);
    cudaFuncSetAttribute(gemm_mma_kernel<64, true>,   cudaFuncAttributeMaxDynamicSharedMemorySize, SMEM2);

    __half *h1, *h2, *a1;
    int *cnt_p;
    cudaGetSymbolAddress((void**)&h1, g_h1);
    cudaGetSymbolAddress((void**)&a1, g_a1);
    cudaGetSymbolAddress((void**)&h2, g_h2);
    cudaGetSymbolAddress((void**)&cnt_p, g_cnt);

    const int TB = 256;
    int gE = (E + TB - 1) / TB;
    int gN = (N_NODES + TB - 1) / TB;
    int gG = (N_NODES + 63) / 64;

    // Serial single-stream schedule: overlapping bandwidth-heavy phases
    // thrashes L2 on this chip (measured +268us in R2). Keep phases ordered.
    cudaMemsetAsync(cnt_p, 0, N_NODES * sizeof(int), 0);
    detect_kernel<<<1, 256>>>((const long long*)ei);  // also zeroes g_total
    count_kernel<<<gE, TB>>>(ei, E);          // also records packed (dst, rank)
    offset_kernel<<<gN, TB>>>();              // block-scan + 391 atomics + dinv
    fill_kernel<<<gE, TB>>>(ei, E);           // atomic-free, src-row-only scatter

    gemm_mma_kernel<128, false><<<gG, 256, SMEM1>>>(x, W1, h1);
    agg128_kernel<<<(N_NODES + 7) / 8, 256>>>(h1, b1, a1);
    gemm_mma_kernel<64, true><<<gG, 256, SMEM2>>>(a1, W2, h2);
    agg64_kernel<<<(N_NODES + 7) / 8, 256>>>(h2, b2, out);
}